// round 11
// baseline (speedup 1.0000x reference)
#include <cuda_runtime.h>
#include <math.h>

// Problem constants (fixed by the reference: B=64, P=1024, D=768)
#define Bsz   64
#define Pseq  1024
#define Ddim  768
#define SPLIT 4                        // CTAs per batch -> 256 CTAs total
#define ROWS_PER_CTA (Pseq / SPLIT)    // 256
#define NWARPS 8
#define NTHREADS (NWARPS * 32)         // 256
#define ROWS_PER_WARP (ROWS_PER_CTA / NWARPS)  // 32 (compile-time!)
#define DPL (Ddim / 32)                // 24 d-elements per lane
#define SLOTS (Bsz * SPLIT)            // 256

#define QE  8                          // e-rows per qw-partial chunk
#define QNC (Ddim / QE)                // 96 producer CTAs

// Scratch (no cudaMalloc allowed) -------------------------------------------
__device__ float g_qw_part[QNC][Ddim];
__device__ float g_qw[Ddim];
__device__ float g_pm[SLOTS];
__device__ float g_pl[SLOTS];
__device__ float g_pacc[SLOTS * Ddim];
__device__ int   g_qdone;              // producers-finished counter (static 0)
__device__ int   g_qflag;              // qw-ready release flag      (static 0)
__device__ int   g_done;               // end-of-kernel reset counter (static 0)

__device__ __forceinline__ int ld_acquire_gpu(const int* p) {
    int v;
    asm volatile("ld.acquire.gpu.global.b32 %0, [%1];" : "=r"(v) : "l"(p));
    return v;
}

__device__ __forceinline__ void load_row(const float* __restrict__ zr, int lane,
                                         float v[DPL]) {
#pragma unroll
    for (int i = 0; i < 6; ++i) {
        float4 t = *reinterpret_cast<const float4*>(&zr[i * 128 + lane * 4]);
        v[i * 4 + 0] = t.x; v[i * 4 + 1] = t.y;
        v[i * 4 + 2] = t.z; v[i * 4 + 3] = t.w;
    }
}

// Kernel 1: qw (embedded, spin-flag) + online-softmax partials -----------------
// One wave (256 CTAs <= 296 slots): producer/consumer flag is deadlock-free.
extern __shared__ float smem[];
__global__ __launch_bounds__(NTHREADS, 2)
void attn_partial_kernel(const float* __restrict__ z,
                         const float* __restrict__ q,
                         const float* __restrict__ W) {
    float* qw_s  = smem;                     // [Ddim]
    float* acc_s = smem + Ddim;              // [NWARPS * Ddim]
    float* m_s   = acc_s + NWARPS * Ddim;    // [NWARPS]
    float* l_s   = m_s + NWARPS;             // [NWARPS]

    const int bid  = blockIdx.x;             // 0..255 ; batch = bid/SPLIT
    const int tid  = threadIdx.x;
    const int w    = tid >> 5;
    const int lane = tid & 31;

    const float* zb = z + ((long)bid * ROWS_PER_CTA + (long)w * ROWS_PER_WARP) * Ddim;

    // Warm L2 with this warp's first 12 rows (36 MB chip-wide = useful attn
    // traffic started at t=0; hides the whole embedded-qw phase).
#pragma unroll
    for (int r = 0; r < 12; ++r) {
        const char* p = (const char*)(zb + (long)r * Ddim) + lane * 128;
        asm volatile("prefetch.global.L2 [%0];" :: "l"(p));
    }

    // ---- embedded qw: producers (CTAs 0..95) --------------------------------
    if (bid < QNC) {
        if (tid < Ddim / 4) {
            const int d4 = tid * 4;
            const int e0 = bid * QE;
            float4 acc = make_float4(0.f, 0.f, 0.f, 0.f);
#pragma unroll
            for (int i = 0; i < QE; ++i) {
                const float qv = __ldg(&q[e0 + i]);
                const float4 wv =
                    *reinterpret_cast<const float4*>(&W[(long)(e0 + i) * Ddim + d4]);
                acc.x += qv * wv.x; acc.y += qv * wv.y;
                acc.z += qv * wv.z; acc.w += qv * wv.w;
            }
            *reinterpret_cast<float4*>(&g_qw_part[bid][d4]) = acc;
        }
        __threadfence();                      // publish partial before counting
        __syncthreads();
        if (tid == 0) atomicAdd(&g_qdone, 1);
    }

    // ---- embedded qw: reducer (CTA 0) ---------------------------------------
    if (bid == 0) {
        if (tid == 0)
            while (ld_acquire_gpu(&g_qdone) != QNC) __nanosleep(64);
        __syncthreads();                      // all partials now visible
        const float sc = rsqrtf((float)Ddim);
#pragma unroll
        for (int k = 0; k < Ddim / NTHREADS; ++k) {     // 3 outputs/thread
            const int d = tid + k * NTHREADS;
            float s = 0.f;
#pragma unroll
            for (int c = 0; c < QNC; ++c) s += g_qw_part[c][d];
            g_qw[d] = s * sc;
        }
        __threadfence();                      // publish g_qw
        __syncthreads();
        if (tid == 0) atomicExch(&g_qflag, 1);   // release
    }

    // ---- everyone waits for qw (overlapped by the z prefetch above) ---------
    if (tid == 0)
        while (ld_acquire_gpu(&g_qflag) == 0) __nanosleep(64);
    __syncthreads();

    for (int t = tid; t < Ddim; t += NTHREADS) qw_s[t] = g_qw[t];
    __syncthreads();

    float qw_r[DPL];
    load_row(qw_s, lane, qw_r);

    float m = -INFINITY, l = 0.f;
    float acc[DPL];
#pragma unroll
    for (int j = 0; j < DPL; ++j) acc[j] = 0.f;

    // ---- proven R6 pairwise main loop ---------------------------------------
    for (int r = 0; r < ROWS_PER_WARP; r += 2) {
        float cv0[DPL], cv1[DPL];
        load_row(zb + (long)r * Ddim,       lane, cv0);   // 12 LDG.128
        load_row(zb + (long)(r + 1) * Ddim, lane, cv1);   // back-to-back

        float s0 = 0.f, s1 = 0.f;
#pragma unroll
        for (int j = 0; j < DPL; ++j) { s0 += cv0[j] * qw_r[j]; s1 += cv1[j] * qw_r[j]; }
#pragma unroll
        for (int o = 16; o; o >>= 1) {        // two butterflies, interleaved
            s0 += __shfl_xor_sync(0xffffffffu, s0, o);
            s1 += __shfl_xor_sync(0xffffffffu, s1, o);
        }

        float m_new = fmaxf(m, fmaxf(s0, s1));
        float alpha = __expf(m - m_new);      // exp(-inf)=0 first pair: safe
        float w0    = __expf(s0 - m_new);
        float w1    = __expf(s1 - m_new);
        l = l * alpha + w0 + w1;
#pragma unroll
        for (int j = 0; j < DPL; ++j)
            acc[j] = acc[j] * alpha + w0 * cv0[j] + w1 * cv1[j];
        m = m_new;
    }

    // Stage per-warp state to smem
#pragma unroll
    for (int i = 0; i < 6; ++i) {
        float4 v = make_float4(acc[i * 4 + 0], acc[i * 4 + 1],
                               acc[i * 4 + 2], acc[i * 4 + 3]);
        *reinterpret_cast<float4*>(&acc_s[w * Ddim + i * 128 + lane * 4]) = v;
    }
    if (lane == 0) { m_s[w] = m; l_s[w] = l; }
    __syncthreads();

    // Cross-warp combine into one partial per CTA
    float M = -INFINITY;
#pragma unroll
    for (int ww = 0; ww < NWARPS; ++ww) M = fmaxf(M, m_s[ww]);

    float ew[NWARPS];
#pragma unroll
    for (int ww = 0; ww < NWARPS; ++ww) ew[ww] = __expf(m_s[ww] - M);

    for (int t = tid; t < Ddim; t += NTHREADS) {
        float sum = 0.f;
#pragma unroll
        for (int ww = 0; ww < NWARPS; ++ww)
            sum += ew[ww] * acc_s[ww * Ddim + t];
        g_pacc[bid * Ddim + t] = sum;
    }
    if (tid == 0) {
        float L = 0.f;
#pragma unroll
        for (int ww = 0; ww < NWARPS; ++ww) L += ew[ww] * l_s[ww];
        g_pm[bid] = M;
        g_pl[bid] = L;
    }

    // ---- reset flags for next graph replay (last CTA out) -------------------
    __syncthreads();
    if (tid == 0) {
        if (atomicAdd(&g_done, 1) == SLOTS - 1) {
            g_done = 0; g_qflag = 0; g_qdone = 0;
        }
    }
}

// Kernel 2: merge SPLIT fixed slots per batch. 256 CTAs x 192 threads. PDL.
__global__ void combine_kernel(float* __restrict__ out) {
    cudaGridDependencySynchronize();          // all attn partials visible
    const int b = blockIdx.x >> 2;
    const int t = (blockIdx.x & 3) * 192 + threadIdx.x;

    float ms[SPLIT], ls[SPLIT];
#pragma unroll
    for (int s = 0; s < SPLIT; ++s) {
        ms[s] = g_pm[b * SPLIT + s];
        ls[s] = g_pl[b * SPLIT + s];
    }
    float M = -INFINITY;
#pragma unroll
    for (int s = 0; s < SPLIT; ++s) M = fmaxf(M, ms[s]);

    float L = 0.f, num = 0.f;
#pragma unroll
    for (int s = 0; s < SPLIT; ++s) {
        float e = __expf(ms[s] - M);
        L   += e * ls[s];
        num += e * g_pacc[(b * SPLIT + s) * Ddim + t];
    }
    out[b * Ddim + t] = num / L;
}

// ----------------------------------------------------------------------------
template <typename F, typename... Args>
static void launch_pdl(F func, dim3 grid, dim3 block, size_t smem, Args... args) {
    cudaLaunchConfig_t cfg = {};
    cfg.gridDim = grid; cfg.blockDim = block;
    cfg.dynamicSmemBytes = smem; cfg.stream = 0;
    cudaLaunchAttribute attr[1];
    attr[0].id = cudaLaunchAttributeProgrammaticStreamSerialization;
    attr[0].val.programmaticStreamSerializationAllowed = 1;
    cfg.attrs = attr; cfg.numAttrs = 1;
    cudaLaunchKernelEx(&cfg, func, args...);
}

extern "C" void kernel_launch(void* const* d_in, const int* in_sizes, int n_in,
                              void* d_out, int out_size) {
    const float* z = nullptr; const float* q = nullptr; const float* W = nullptr;
    for (int i = 0; i < n_in; ++i) {
        if (in_sizes[i] == Bsz * Pseq * Ddim)      z = (const float*)d_in[i];
        else if (in_sizes[i] == Ddim)              q = (const float*)d_in[i];
        else if (in_sizes[i] == Ddim * Ddim)       W = (const float*)d_in[i];
    }
    float* out = (float*)d_out;

    const int smem_bytes = (Ddim + NWARPS * Ddim + 2 * NWARPS) * (int)sizeof(float);
    cudaFuncSetAttribute(attn_partial_kernel,
                         cudaFuncAttributeMaxDynamicSharedMemorySize, smem_bytes);

    attn_partial_kernel<<<Bsz * SPLIT, NTHREADS, smem_bytes>>>(z, q, W);
    launch_pdl(combine_kernel, dim3(Bsz * SPLIT), dim3(192), (size_t)0, out);
}

// round 12
// speedup vs baseline: 1.1770x; 1.1770x over previous
#include <cuda_runtime.h>
#include <math.h>

// Problem constants (fixed by the reference: B=64, P=1024, D=768)
#define Bsz   64
#define Pseq  1024
#define Ddim  768
#define SPLIT 4                        // CTAs per batch -> 256 CTAs total
#define ROWS_PER_CTA (Pseq / SPLIT)    // 256
#define NWARPS 8
#define NTHREADS (NWARPS * 32)         // 256
#define ROWS_PER_WARP (ROWS_PER_CTA / NWARPS)  // 32 (compile-time!)
#define DPL (Ddim / 32)                // 24 d-elements per lane
#define SLOTS (Bsz * SPLIT)            // 256

#define QE  8                          // e-rows per qw-partial chunk
#define QNC (Ddim / QE)                // 96 chunks

// Scratch (no cudaMalloc allowed) -------------------------------------------
__device__ float g_qw_part[QNC][Ddim];
__device__ float g_qw[Ddim];
__device__ float g_pm[SLOTS];
__device__ float g_pl[SLOTS];
__device__ float g_pacc[SLOTS * Ddim];

// Kernel 1a: partial qw. Early trigger -> qw_reduce (and transitively attn)
// may launch and run preambles while this executes.
__global__ void qw_part_kernel(const float* __restrict__ q,
                               const float* __restrict__ W) {
    cudaTriggerProgrammaticLaunchCompletion();   // release dependent launch NOW
    const int d4 = threadIdx.x * 4;
    const int e0 = blockIdx.x * QE;
    float4 acc = make_float4(0.f, 0.f, 0.f, 0.f);
#pragma unroll
    for (int i = 0; i < QE; ++i) {
        const float qv = __ldg(&q[e0 + i]);
        const float4 w = *reinterpret_cast<const float4*>(&W[(long)(e0 + i) * Ddim + d4]);
        acc.x += qv * w.x; acc.y += qv * w.y;
        acc.z += qv * w.z; acc.w += qv * w.w;
    }
    *reinterpret_cast<float4*>(&g_qw_part[blockIdx.x][d4]) = acc;
}

// Kernel 1b: fold 96 partials. Trigger at entry (releases attn), THEN wait.
__global__ void qw_reduce_kernel() {
    cudaTriggerProgrammaticLaunchCompletion();   // let attn launch + prefetch
    cudaGridDependencySynchronize();             // wait for qw_part results
    const int d = blockIdx.x * 192 + threadIdx.x;
    float acc = 0.f;
#pragma unroll
    for (int c = 0; c < QNC; ++c) acc += g_qw_part[c][d];
    g_qw[d] = acc * rsqrtf((float)Ddim);
}

// Kernel 2: online-softmax partials. Preamble prefetches first 8 z-rows
// (z is NOT written by the qw kernels -> legal before griddepsync), so the
// whole qw phase is hidden under useful z DRAM streaming.
__device__ __forceinline__ void load_row(const float* __restrict__ zr, int lane,
                                         float v[DPL]) {
#pragma unroll
    for (int i = 0; i < 6; ++i) {
        float4 t = *reinterpret_cast<const float4*>(&zr[i * 128 + lane * 4]);
        v[i * 4 + 0] = t.x; v[i * 4 + 1] = t.y;
        v[i * 4 + 2] = t.z; v[i * 4 + 3] = t.w;
    }
}

extern __shared__ float smem[];
__global__ __launch_bounds__(NTHREADS, 2)
void attn_partial_kernel(const float* __restrict__ z) {
    float* qw_s  = smem;                     // [Ddim]
    float* acc_s = smem + Ddim;              // [NWARPS * Ddim]
    float* m_s   = acc_s + NWARPS * Ddim;    // [NWARPS]
    float* l_s   = m_s + NWARPS;             // [NWARPS]

    const int bid  = blockIdx.x;             // 0..255 ; batch = bid/SPLIT
    const int tid  = threadIdx.x;
    const int w    = tid >> 5;
    const int lane = tid & 31;

    const float* zb = z + ((long)bid * ROWS_PER_CTA + (long)w * ROWS_PER_WARP) * Ddim;

    // Preamble: warm L2 with this warp's first 8 rows (48 MB chip-wide),
    // overlapping qw_part + qw_reduce execution.
#pragma unroll
    for (int r = 0; r < 8; ++r) {
        const char* p = (const char*)(zb + (long)r * Ddim) + lane * 128;
        asm volatile("prefetch.global.L2 [%0];" :: "l"(p));
    }

    cudaTriggerProgrammaticLaunchCompletion();   // release combine launch
    cudaGridDependencySynchronize();             // qw results now visible

    for (int t = tid; t < Ddim; t += NTHREADS) qw_s[t] = g_qw[t];
    __syncthreads();

    float qw_r[DPL];
    load_row(qw_s, lane, qw_r);

    float m = -INFINITY, l = 0.f;
    float acc[DPL];
#pragma unroll
    for (int j = 0; j < DPL; ++j) acc[j] = 0.f;

    // ---- proven R6 pairwise main loop ---------------------------------------
    for (int r = 0; r < ROWS_PER_WARP; r += 2) {
        float cv0[DPL], cv1[DPL];
        load_row(zb + (long)r * Ddim,       lane, cv0);   // 12 LDG.128
        load_row(zb + (long)(r + 1) * Ddim, lane, cv1);   // back-to-back

        float s0 = 0.f, s1 = 0.f;
#pragma unroll
        for (int j = 0; j < DPL; ++j) { s0 += cv0[j] * qw_r[j]; s1 += cv1[j] * qw_r[j]; }
#pragma unroll
        for (int o = 16; o; o >>= 1) {        // two butterflies, interleaved
            s0 += __shfl_xor_sync(0xffffffffu, s0, o);
            s1 += __shfl_xor_sync(0xffffffffu, s1, o);
        }

        float m_new = fmaxf(m, fmaxf(s0, s1));
        float alpha = __expf(m - m_new);      // exp(-inf)=0 first pair: safe
        float w0    = __expf(s0 - m_new);
        float w1    = __expf(s1 - m_new);
        l = l * alpha + w0 + w1;
#pragma unroll
        for (int j = 0; j < DPL; ++j)
            acc[j] = acc[j] * alpha + w0 * cv0[j] + w1 * cv1[j];
        m = m_new;
    }

    // Stage per-warp state to smem
#pragma unroll
    for (int i = 0; i < 6; ++i) {
        float4 v = make_float4(acc[i * 4 + 0], acc[i * 4 + 1],
                               acc[i * 4 + 2], acc[i * 4 + 3]);
        *reinterpret_cast<float4*>(&acc_s[w * Ddim + i * 128 + lane * 4]) = v;
    }
    if (lane == 0) { m_s[w] = m; l_s[w] = l; }
    __syncthreads();

    // Cross-warp combine into one partial per CTA
    float M = -INFINITY;
#pragma unroll
    for (int ww = 0; ww < NWARPS; ++ww) M = fmaxf(M, m_s[ww]);

    float ew[NWARPS];
#pragma unroll
    for (int ww = 0; ww < NWARPS; ++ww) ew[ww] = __expf(m_s[ww] - M);

    for (int t = tid; t < Ddim; t += NTHREADS) {
        float sum = 0.f;
#pragma unroll
        for (int ww = 0; ww < NWARPS; ++ww)
            sum += ew[ww] * acc_s[ww * Ddim + t];
        g_pacc[bid * Ddim + t] = sum;
    }
    if (tid == 0) {
        float L = 0.f;
#pragma unroll
        for (int ww = 0; ww < NWARPS; ++ww) L += ew[ww] * l_s[ww];
        g_pm[bid] = M;
        g_pl[bid] = L;
    }
}

// Kernel 3: merge SPLIT fixed slots per batch. 256 CTAs x 192 threads. PDL.
__global__ void combine_kernel(float* __restrict__ out) {
    cudaGridDependencySynchronize();          // all attn partials visible
    const int b = blockIdx.x >> 2;
    const int t = (blockIdx.x & 3) * 192 + threadIdx.x;

    float ms[SPLIT], ls[SPLIT];
#pragma unroll
    for (int s = 0; s < SPLIT; ++s) {
        ms[s] = g_pm[b * SPLIT + s];
        ls[s] = g_pl[b * SPLIT + s];
    }
    float M = -INFINITY;
#pragma unroll
    for (int s = 0; s < SPLIT; ++s) M = fmaxf(M, ms[s]);

    float L = 0.f, num = 0.f;
#pragma unroll
    for (int s = 0; s < SPLIT; ++s) {
        float e = __expf(ms[s] - M);
        L   += e * ls[s];
        num += e * g_pacc[(b * SPLIT + s) * Ddim + t];
    }
    out[b * Ddim + t] = num / L;
}

// ----------------------------------------------------------------------------
template <typename F, typename... Args>
static void launch_pdl(F func, dim3 grid, dim3 block, size_t smem, Args... args) {
    cudaLaunchConfig_t cfg = {};
    cfg.gridDim = grid; cfg.blockDim = block;
    cfg.dynamicSmemBytes = smem; cfg.stream = 0;
    cudaLaunchAttribute attr[1];
    attr[0].id = cudaLaunchAttributeProgrammaticStreamSerialization;
    attr[0].val.programmaticStreamSerializationAllowed = 1;
    cfg.attrs = attr; cfg.numAttrs = 1;
    cudaLaunchKernelEx(&cfg, func, args...);
}

extern "C" void kernel_launch(void* const* d_in, const int* in_sizes, int n_in,
                              void* d_out, int out_size) {
    const float* z = nullptr; const float* q = nullptr; const float* W = nullptr;
    for (int i = 0; i < n_in; ++i) {
        if (in_sizes[i] == Bsz * Pseq * Ddim)      z = (const float*)d_in[i];
        else if (in_sizes[i] == Ddim)              q = (const float*)d_in[i];
        else if (in_sizes[i] == Ddim * Ddim)       W = (const float*)d_in[i];
    }
    float* out = (float*)d_out;

    const int smem_bytes = (Ddim + NWARPS * Ddim + 2 * NWARPS) * (int)sizeof(float);
    cudaFuncSetAttribute(attn_partial_kernel,
                         cudaFuncAttributeMaxDynamicSharedMemorySize, smem_bytes);

    qw_part_kernel<<<QNC, Ddim / 4>>>(q, W);
    launch_pdl(qw_reduce_kernel, dim3(4), dim3(192), 0);
    launch_pdl(attn_partial_kernel, dim3(Bsz * SPLIT), dim3(NTHREADS),
               (size_t)smem_bytes, z);
    launch_pdl(combine_kernel, dim3(Bsz * SPLIT), dim3(192), (size_t)0, out);
}

// round 13
// speedup vs baseline: 1.1840x; 1.0059x over previous
#include <cuda_runtime.h>
#include <math.h>

// Problem constants (fixed by the reference: B=64, P=1024, D=768)
#define Bsz   64
#define Pseq  1024
#define Ddim  768
#define SPLIT 4                        // CTAs per batch -> 256 CTAs total
#define ROWS_PER_CTA (Pseq / SPLIT)    // 256
#define NWARPS 8
#define NTHREADS (NWARPS * 32)         // 256
#define ROWS_PER_WARP (ROWS_PER_CTA / NWARPS)  // 32 (compile-time!)
#define DPL (Ddim / 32)                // 24 d-elements per lane
#define SLOTS (Bsz * SPLIT)            // 256

#define QE  8                          // e-rows per qw-partial chunk
#define QNC (Ddim / QE)                // 96 chunks

// Scratch (no cudaMalloc allowed) -------------------------------------------
__device__ float g_qw_part[QNC][Ddim];
__device__ float g_qw[Ddim];
__device__ float g_pm[SLOTS];
__device__ float g_pl[SLOTS];
__device__ float g_pacc[SLOTS * Ddim];

// Kernel 1a: partial qw. grid=96, block=192; 8 independent LDG.128 per thread.
__global__ void qw_part_kernel(const float* __restrict__ q,
                               const float* __restrict__ W) {
    const int d4 = threadIdx.x * 4;
    const int e0 = blockIdx.x * QE;
    float4 acc = make_float4(0.f, 0.f, 0.f, 0.f);
#pragma unroll
    for (int i = 0; i < QE; ++i) {
        const float qv = __ldg(&q[e0 + i]);
        const float4 w = *reinterpret_cast<const float4*>(&W[(long)(e0 + i) * Ddim + d4]);
        acc.x += qv * w.x; acc.y += qv * w.y;
        acc.z += qv * w.z; acc.w += qv * w.w;
    }
    *reinterpret_cast<float4*>(&g_qw_part[blockIdx.x][d4]) = acc;
}

// Kernel 1b: fold 96 partials (independent, L2-hot). grid=4, block=192.
__global__ void qw_reduce_kernel() {
    const int d = blockIdx.x * 192 + threadIdx.x;
    float acc = 0.f;
#pragma unroll
    for (int c = 0; c < QNC; ++c) acc += g_qw_part[c][d];
    g_qw[d] = acc * rsqrtf((float)Ddim);
}

// Kernel 2: per-(batch, quarter) online-softmax pooled partial -----------------
// R6 pairwise loop + L1 prefetch ONE pair ahead: per lane one 128B line per
// row (24 active lines cover the 3KB row; lanes 24-31 spill into the next
// row's first KB — still useful). Converts exposed L2->SM latency into L1 hits.
__device__ __forceinline__ void load_row(const float* __restrict__ zr, int lane,
                                         float v[DPL]) {
#pragma unroll
    for (int i = 0; i < 6; ++i) {
        float4 t = *reinterpret_cast<const float4*>(&zr[i * 128 + lane * 4]);
        v[i * 4 + 0] = t.x; v[i * 4 + 1] = t.y;
        v[i * 4 + 2] = t.z; v[i * 4 + 3] = t.w;
    }
}

extern __shared__ float smem[];
__global__ __launch_bounds__(NTHREADS, 2)
void attn_partial_kernel(const float* __restrict__ z) {
    float* qw_s  = smem;                     // [Ddim]
    float* acc_s = smem + Ddim;              // [NWARPS * Ddim]
    float* m_s   = acc_s + NWARPS * Ddim;    // [NWARPS]
    float* l_s   = m_s + NWARPS;             // [NWARPS]

    const int bid  = blockIdx.x;             // 0..255 ; batch = bid/SPLIT
    const int tid  = threadIdx.x;
    const int w    = tid >> 5;
    const int lane = tid & 31;

    const float* zb = z + ((long)bid * ROWS_PER_CTA + (long)w * ROWS_PER_WARP) * Ddim;

    // Prime L1 with the first pair before the qw smem stage.
    {
        const char* p0 = (const char*)zb + lane * 128;
        const char* p1 = (const char*)(zb + Ddim) + lane * 128;
        asm volatile("prefetch.global.L1 [%0];" :: "l"(p0));
        asm volatile("prefetch.global.L1 [%0];" :: "l"(p1));
    }

    for (int t = tid; t < Ddim; t += NTHREADS) qw_s[t] = g_qw[t];
    __syncthreads();

    float qw_r[DPL];
    load_row(qw_s, lane, qw_r);

    float m = -INFINITY, l = 0.f;
    float acc[DPL];
#pragma unroll
    for (int j = 0; j < DPL; ++j) acc[j] = 0.f;

    for (int r = 0; r < ROWS_PER_WARP; r += 2) {
        // L1 prefetch next pair (reg-free, no scoreboard)
        if (r + 2 < ROWS_PER_WARP) {
            const char* p0 = (const char*)(zb + (long)(r + 2) * Ddim) + lane * 128;
            const char* p1 = (const char*)(zb + (long)(r + 3) * Ddim) + lane * 128;
            asm volatile("prefetch.global.L1 [%0];" :: "l"(p0));
            asm volatile("prefetch.global.L1 [%0];" :: "l"(p1));
        }

        float cv0[DPL], cv1[DPL];
        load_row(zb + (long)r * Ddim,       lane, cv0);   // 12 LDG.128
        load_row(zb + (long)(r + 1) * Ddim, lane, cv1);   // back-to-back

        float s0 = 0.f, s1 = 0.f;
#pragma unroll
        for (int j = 0; j < DPL; ++j) { s0 += cv0[j] * qw_r[j]; s1 += cv1[j] * qw_r[j]; }
#pragma unroll
        for (int o = 16; o; o >>= 1) {        // two butterflies, interleaved
            s0 += __shfl_xor_sync(0xffffffffu, s0, o);
            s1 += __shfl_xor_sync(0xffffffffu, s1, o);
        }

        float m_new = fmaxf(m, fmaxf(s0, s1));
        float alpha = __expf(m - m_new);      // exp(-inf)=0 first pair: safe
        float w0    = __expf(s0 - m_new);
        float w1    = __expf(s1 - m_new);
        l = l * alpha + w0 + w1;
#pragma unroll
        for (int j = 0; j < DPL; ++j)
            acc[j] = acc[j] * alpha + w0 * cv0[j] + w1 * cv1[j];
        m = m_new;
    }

    // Stage per-warp state to smem
#pragma unroll
    for (int i = 0; i < 6; ++i) {
        float4 v = make_float4(acc[i * 4 + 0], acc[i * 4 + 1],
                               acc[i * 4 + 2], acc[i * 4 + 3]);
        *reinterpret_cast<float4*>(&acc_s[w * Ddim + i * 128 + lane * 4]) = v;
    }
    if (lane == 0) { m_s[w] = m; l_s[w] = l; }
    __syncthreads();

    // Cross-warp combine into one partial per CTA
    float M = -INFINITY;
#pragma unroll
    for (int ww = 0; ww < NWARPS; ++ww) M = fmaxf(M, m_s[ww]);

    float ew[NWARPS];
#pragma unroll
    for (int ww = 0; ww < NWARPS; ++ww) ew[ww] = __expf(m_s[ww] - M);

    for (int t = tid; t < Ddim; t += NTHREADS) {
        float sum = 0.f;
#pragma unroll
        for (int ww = 0; ww < NWARPS; ++ww)
            sum += ew[ww] * acc_s[ww * Ddim + t];
        g_pacc[bid * Ddim + t] = sum;
    }
    if (tid == 0) {
        float L = 0.f;
#pragma unroll
        for (int ww = 0; ww < NWARPS; ++ww) L += ew[ww] * l_s[ww];
        g_pm[bid] = M;
        g_pl[bid] = L;
    }
}

// Kernel 3: merge SPLIT fixed slots per batch. 256 CTAs x 192 threads ----------
__global__ void combine_kernel(float* __restrict__ out) {
    const int b = blockIdx.x >> 2;
    const int t = (blockIdx.x & 3) * 192 + threadIdx.x;

    float ms[SPLIT], ls[SPLIT];
#pragma unroll
    for (int s = 0; s < SPLIT; ++s) {
        ms[s] = g_pm[b * SPLIT + s];
        ls[s] = g_pl[b * SPLIT + s];
    }
    float M = -INFINITY;
#pragma unroll
    for (int s = 0; s < SPLIT; ++s) M = fmaxf(M, ms[s]);

    float L = 0.f, num = 0.f;
#pragma unroll
    for (int s = 0; s < SPLIT; ++s) {
        float e = __expf(ms[s] - M);
        L   += e * ls[s];
        num += e * g_pacc[(b * SPLIT + s) * Ddim + t];
    }
    out[b * Ddim + t] = num / L;
}

// ----------------------------------------------------------------------------
extern "C" void kernel_launch(void* const* d_in, const int* in_sizes, int n_in,
                              void* d_out, int out_size) {
    const float* z = nullptr; const float* q = nullptr; const float* W = nullptr;
    for (int i = 0; i < n_in; ++i) {
        if (in_sizes[i] == Bsz * Pseq * Ddim)      z = (const float*)d_in[i];
        else if (in_sizes[i] == Ddim)              q = (const float*)d_in[i];
        else if (in_sizes[i] == Ddim * Ddim)       W = (const float*)d_in[i];
    }
    float* out = (float*)d_out;

    const int smem_bytes = (Ddim + NWARPS * Ddim + 2 * NWARPS) * (int)sizeof(float);
    cudaFuncSetAttribute(attn_partial_kernel,
                         cudaFuncAttributeMaxDynamicSharedMemorySize, smem_bytes);

    qw_part_kernel<<<QNC, Ddim / 4>>>(q, W);
    qw_reduce_kernel<<<4, 192>>>();
    attn_partial_kernel<<<Bsz * SPLIT, NTHREADS, smem_bytes>>>(z);
    combine_kernel<<<Bsz * SPLIT, 192>>>(out);
}